// round 16
// baseline (speedup 1.0000x reference)
#include <cuda_runtime.h>
#include <cuda_bf16.h>

// MultiLoss: actor_loss = (1/B) * sum_{b,t} log(policies[b,t,actions[b,t]]) * (ea[b]-adv[b])
// B=4096, T=200, A=64. actions int32.
// Engine: EPT=4 / 800 CTAs / 256 thr + L2 evict_last retention (proven optimum).
// Key fact: base = 4*tid and 4 | 200  =>  all 4 elements of a thread share one batch
// row b = tid/50. One ea + one adv load per thread (was 8), zero per-element divisions.
// Reduction: plain partial stores + tiny reduce node (proven fastest topology).

#define B_DIM 4096
#define T_DIM 200
#define A_DIM 64
#define TOTAL (B_DIM * T_DIM)          // 819200
#define THREADS 256
#define EPT 4                           // elements per thread (int4 action load)
#define GRID (TOTAL / (THREADS * EPT))  // 800, exact

__device__ float g_partials[GRID];

__device__ __forceinline__ unsigned long long make_evict_last_policy() {
    unsigned long long pol;
    asm volatile("createpolicy.fractional.L2::evict_last.b64 %0, 1.0;" : "=l"(pol));
    return pol;
}

__device__ __forceinline__ float ldg_el(const float* p, unsigned long long pol) {
    float v;
    asm volatile("ld.global.nc.L2::cache_hint.f32 %0, [%1], %2;"
                 : "=f"(v) : "l"(p), "l"(pol));
    return v;
}

__device__ __forceinline__ int4 ldg_el_i4(const int4* p, unsigned long long pol) {
    int4 v;
    asm volatile("ld.global.nc.L2::cache_hint.v4.s32 {%0,%1,%2,%3}, [%4], %5;"
                 : "=r"(v.x), "=r"(v.y), "=r"(v.z), "=r"(v.w) : "l"(p), "l"(pol));
    return v;
}

__global__ __launch_bounds__(THREADS) void multiloss_kernel(
    const float* __restrict__ policies,   // [B, T, A] f32
    const int*   __restrict__ actions,    // [B, T] i32
    const float* __restrict__ ea,         // [B]
    const float* __restrict__ adv)        // [B]
{
    const int tid  = blockIdx.x * THREADS + threadIdx.x;
    const int base = tid * EPT;           // first flat element index (b*T + t)

    const unsigned long long pol = make_evict_last_policy();

    // 1 coalesced 16B load -> 4 action indices (retained in L2)
    const int4 act = ldg_el_i4(reinterpret_cast<const int4*>(actions) + tid, pol);

    // 4 independent scattered gathers, biased to stay L2-resident
    const float p0 = ldg_el(&policies[(size_t)(base + 0) * A_DIM + act.x], pol);
    const float p1 = ldg_el(&policies[(size_t)(base + 1) * A_DIM + act.y], pol);
    const float p2 = ldg_el(&policies[(size_t)(base + 2) * A_DIM + act.z], pol);
    const float p3 = ldg_el(&policies[(size_t)(base + 3) * A_DIM + act.w], pol);

    // All 4 elements share one batch row: b = (4*tid)/200 = tid/50 exactly.
    const int   b = tid / 50;
    const float w = __ldg(&ea[b]) - __ldg(&adv[b]);

    // w * sum(log p)  — algebraically identical to per-element weighting
    float lsum = __logf(p0);
    lsum += __logf(p1);
    lsum += __logf(p2);
    lsum += __logf(p3);
    float acc = lsum * w;

    // warp reduce
    #pragma unroll
    for (int o = 16; o > 0; o >>= 1)
        acc += __shfl_down_sync(0xffffffff, acc, o);

    __shared__ float ws[THREADS / 32];
    const int wid = threadIdx.x >> 5;
    const int lid = threadIdx.x & 31;
    if (lid == 0) ws[wid] = acc;
    __syncthreads();

    if (threadIdx.x == 0) {
        float s = 0.0f;
        #pragma unroll
        for (int i = 0; i < THREADS / 32; i++) s += ws[i];
        g_partials[blockIdx.x] = s;   // plain store; overwritten every replay
    }
}

// 800 floats -> scalar. One CTA, 256 threads: vectorized float4 loads (L2 hits).
__global__ __launch_bounds__(THREADS) void reduce_kernel(float* __restrict__ out) {
    const float4* p4 = reinterpret_cast<const float4*>(g_partials);  // 200 float4s
    float s = 0.0f;
    if (threadIdx.x < GRID / 4) {   // 200 threads
        const float4 v = p4[threadIdx.x];
        s = (v.x + v.y) + (v.z + v.w);
    }
    #pragma unroll
    for (int o = 16; o > 0; o >>= 1)
        s += __shfl_down_sync(0xffffffff, s, o);

    __shared__ float ws[THREADS / 32];
    const int wid = threadIdx.x >> 5;
    const int lid = threadIdx.x & 31;
    if (lid == 0) ws[wid] = s;
    __syncthreads();

    if (threadIdx.x == 0) {
        float r = 0.0f;
        #pragma unroll
        for (int i = 0; i < THREADS / 32; i++) r += ws[i];
        out[0] = r * (1.0f / (float)B_DIM);
    }
}

extern "C" void kernel_launch(void* const* d_in, const int* in_sizes, int n_in,
                              void* d_out, int out_size) {
    const float* policies = (const float*)d_in[0];
    const int*   actions  = (const int*)d_in[1];
    const float* ea       = (const float*)d_in[2];
    const float* adv      = (const float*)d_in[3];
    float* out = (float*)d_out;

    multiloss_kernel<<<GRID, THREADS>>>(policies, actions, ea, adv);
    reduce_kernel<<<1, THREADS>>>(out);
}

// round 17
// speedup vs baseline: 1.1569x; 1.1569x over previous
#include <cuda_runtime.h>
#include <cuda_bf16.h>

// MultiLoss: actor_loss = (1/B) * sum_{b,t} log(policies[b,t,actions[b,t]]) * (ea[b]-adv[b])
// B=4096, T=200, A=64. actions int32.
// Engine: EPT=4 / 800 CTAs / 256 thr + L2 evict_last retention.
// Micro-opts: one batch row per thread (b=tid/50, 2 weight loads not 8);
//             log of product (1 MUFU lg2 instead of 4).
// Reduction: plain partial stores + 1-warp reduce node.

#define B_DIM 4096
#define T_DIM 200
#define A_DIM 64
#define TOTAL (B_DIM * T_DIM)          // 819200
#define THREADS 256
#define EPT 4                           // elements per thread (int4 action load)
#define GRID (TOTAL / (THREADS * EPT))  // 800, exact

__device__ float g_partials[GRID];

__device__ __forceinline__ unsigned long long make_evict_last_policy() {
    unsigned long long pol;
    asm volatile("createpolicy.fractional.L2::evict_last.b64 %0, 1.0;" : "=l"(pol));
    return pol;
}

__device__ __forceinline__ float ldg_el(const float* p, unsigned long long pol) {
    float v;
    asm volatile("ld.global.nc.L2::cache_hint.f32 %0, [%1], %2;"
                 : "=f"(v) : "l"(p), "l"(pol));
    return v;
}

__device__ __forceinline__ int4 ldg_el_i4(const int4* p, unsigned long long pol) {
    int4 v;
    asm volatile("ld.global.nc.L2::cache_hint.v4.s32 {%0,%1,%2,%3}, [%4], %5;"
                 : "=r"(v.x), "=r"(v.y), "=r"(v.z), "=r"(v.w) : "l"(p), "l"(pol));
    return v;
}

__global__ __launch_bounds__(THREADS) void multiloss_kernel(
    const float* __restrict__ policies,   // [B, T, A] f32
    const int*   __restrict__ actions,    // [B, T] i32
    const float* __restrict__ ea,         // [B]
    const float* __restrict__ adv)        // [B]
{
    const int tid  = blockIdx.x * THREADS + threadIdx.x;
    const int base = tid * EPT;           // first flat element index (b*T + t)

    const unsigned long long pol = make_evict_last_policy();

    // 1 coalesced 16B load -> 4 action indices (retained in L2)
    const int4 act = ldg_el_i4(reinterpret_cast<const int4*>(actions) + tid, pol);

    // 4 independent scattered gathers, biased to stay L2-resident
    const float p0 = ldg_el(&policies[(size_t)(base + 0) * A_DIM + act.x], pol);
    const float p1 = ldg_el(&policies[(size_t)(base + 1) * A_DIM + act.y], pol);
    const float p2 = ldg_el(&policies[(size_t)(base + 2) * A_DIM + act.z], pol);
    const float p3 = ldg_el(&policies[(size_t)(base + 3) * A_DIM + act.w], pol);

    // All 4 elements share one batch row: b = (4*tid)/200 = tid/50 exactly.
    const int   b = tid / 50;
    const float w = __ldg(&ea[b]) - __ldg(&adv[b]);

    // log(p0*p1*p2*p3) == sum(log pi); product in [1e-16, 1] -> safe in f32.
    const float prod = (p0 * p1) * (p2 * p3);
    float acc = __logf(prod) * w;

    // warp reduce
    #pragma unroll
    for (int o = 16; o > 0; o >>= 1)
        acc += __shfl_down_sync(0xffffffff, acc, o);

    __shared__ float ws[THREADS / 32];
    const int wid = threadIdx.x >> 5;
    const int lid = threadIdx.x & 31;
    if (lid == 0) ws[wid] = acc;
    __syncthreads();

    if (threadIdx.x == 0) {
        float s = 0.0f;
        #pragma unroll
        for (int i = 0; i < THREADS / 32; i++) s += ws[i];
        g_partials[blockIdx.x] = s;   // plain store; overwritten every replay
    }
}

// 800 floats -> scalar. ONE WARP: no smem, no __syncthreads; launch latency
// dominates this node anyway.
__global__ __launch_bounds__(32) void reduce_kernel(float* __restrict__ out) {
    const float4* p4 = reinterpret_cast<const float4*>(g_partials);  // 200 float4s
    float s = 0.0f;
    #pragma unroll
    for (int i = 0; i < 7; i++) {                 // 7*32=224 >= 200 slots
        const int idx = threadIdx.x + i * 32;
        if (idx < GRID / 4) {
            const float4 v = p4[idx];
            s += (v.x + v.y) + (v.z + v.w);
        }
    }
    #pragma unroll
    for (int o = 16; o > 0; o >>= 1)
        s += __shfl_down_sync(0xffffffff, s, o);

    if (threadIdx.x == 0)
        out[0] = s * (1.0f / (float)B_DIM);
}

extern "C" void kernel_launch(void* const* d_in, const int* in_sizes, int n_in,
                              void* d_out, int out_size) {
    const float* policies = (const float*)d_in[0];
    const int*   actions  = (const int*)d_in[1];
    const float* ea       = (const float*)d_in[2];
    const float* adv      = (const float*)d_in[3];
    float* out = (float*)d_out;

    multiloss_kernel<<<GRID, THREADS>>>(policies, actions, ea, adv);
    reduce_kernel<<<1, 32>>>(out);
}